// round 1
// baseline (speedup 1.0000x reference)
#include <cuda_runtime.h>
#include <cuda_bf16.h>

// Problem constants
#define B 8
#define N 2048
#define D 1024
#define G 8
#define CAP 320
#define NTOK (B*N)          // 16384
#define F4_PER_TOK (G*CAP/4) // 640

// Scratch (device globals; no allocation allowed)
__device__ int    g_pack[NTOK];   // i1 | i2<<4 | use2<<8
__device__ float2 g_gates[NTOK];  // (g1n, g2n)
__device__ int2   g_off[NTOK];    // flat offsets within token slab, -1 if dropped

// ---------------------------------------------------------------------------
// K1: per-token logits (dot 1024 x 8), softmax, top1/top2, renorm + threshold
// warp per token; W stored transposed in smem for conflict-free LDS.128
// ---------------------------------------------------------------------------
__global__ __launch_bounds__(256) void k_gate(const float* __restrict__ x,
                                              const float* __restrict__ w) {
    __shared__ float Wt[G * D];  // [e][k], 32 KB
    int tid = threadIdx.x;
    for (int i = tid; i < G * D; i += 256) {
        int k = i >> 3, e = i & 7;          // w is [D, G] row-major
        Wt[e * D + k] = w[i];
    }
    __syncthreads();

    int warp = tid >> 5, lane = tid & 31;
    int t = blockIdx.x * 8 + warp;          // 2048 blocks * 8 warps = 16384 tokens
    const float4* xr = (const float4*)(x + (size_t)t * D);

    float acc[G];
#pragma unroll
    for (int e = 0; e < G; e++) acc[e] = 0.f;

#pragma unroll
    for (int i = 0; i < 8; i++) {
        int f4 = i * 32 + lane;             // coalesced 512B per warp-iter
        float4 xv = xr[f4];
        int k0 = f4 * 4;
#pragma unroll
        for (int e = 0; e < G; e++) {
            float4 wv = *(const float4*)&Wt[e * D + k0];
            acc[e] += xv.x * wv.x + xv.y * wv.y + xv.z * wv.z + xv.w * wv.w;
        }
    }
    // warp reduce 8 accumulators
#pragma unroll
    for (int e = 0; e < G; e++) {
#pragma unroll
        for (int o = 16; o > 0; o >>= 1)
            acc[e] += __shfl_down_sync(0xffffffffu, acc[e], o);
    }

    if (lane == 0) {
        float m = acc[0];
#pragma unroll
        for (int e = 1; e < G; e++) m = fmaxf(m, acc[e]);
        float p[G];
        float s = 0.f;
#pragma unroll
        for (int e = 0; e < G; e++) { p[e] = expf(acc[e] - m); s += p[e]; }
        float inv = 1.f / s;
#pragma unroll
        for (int e = 0; e < G; e++) p[e] *= inv;

        // top-1 (first-max tie-break like jnp.argmax)
        int i1 = 0; float g1 = p[0];
#pragma unroll
        for (int e = 1; e < G; e++) if (p[e] > g1) { g1 = p[e]; i1 = e; }
        // top-2 among the rest
        int i2 = 0; float g2 = -1.f;
#pragma unroll
        for (int e = 0; e < G; e++)
            if (e != i1 && p[e] > g2) { g2 = p[e]; i2 = e; }

        // faithful renorm order from reference
        float g1n = g1 / (g1 + g2 + 1e-9f);
        float g2n = g2 / (g1n + g2 + 1e-9f);
        int use2 = (g2n > 0.2f) ? 1 : 0;

        g_pack[t] = i1 | (i2 << 4) | (use2 << 8);
        g_gates[t] = make_float2(g1n, g2n);
    }
}

// ---------------------------------------------------------------------------
// K2: per-batch token scan. 1 block per batch, 256 threads x 8 tokens each.
// 8 expert counters packed as 2 x u64 (16 bits/expert, max 2048 fits).
// ---------------------------------------------------------------------------
__global__ __launch_bounds__(256) void k_scan() {
    __shared__ unsigned long long sl[256], sh[256];
    __shared__ int count1[G];

    int b = blockIdx.x, tid = threadIdx.x;
    int base = b * N + tid * 8;

    int pk[8];
#pragma unroll
    for (int j = 0; j < 8; j++) pk[j] = g_pack[base + j];

    // ---- pass 1: top-1 positions ----
    unsigned long long lo = 0, hi = 0;
#pragma unroll
    for (int j = 0; j < 8; j++) {
        int i1 = pk[j] & 15;
        if (i1 < 4) lo += 1ULL << (i1 * 16); else hi += 1ULL << ((i1 - 4) * 16);
    }
    unsigned long long mylo = lo, myhi = hi;
    sl[tid] = lo; sh[tid] = hi;
    __syncthreads();
    for (int o = 1; o < 256; o <<= 1) {
        unsigned long long a = 0, c = 0;
        if (tid >= o) { a = sl[tid - o]; c = sh[tid - o]; }
        __syncthreads();
        if (tid >= o) { sl[tid] += a; sh[tid] += c; }
        __syncthreads();
    }
    unsigned long long exlo = sl[tid] - mylo, exhi = sh[tid] - myhi;
    if (tid == 255) {
#pragma unroll
        for (int e = 0; e < 4; e++) {
            count1[e]     = min((int)((sl[255] >> (e * 16)) & 0xFFFF), CAP);
            count1[e + 4] = min((int)((sh[255] >> (e * 16)) & 0xFFFF), CAP);
        }
    }
    int pos1[8];
    {
        unsigned long long rlo = exlo, rhi = exhi;
#pragma unroll
        for (int j = 0; j < 8; j++) {
            int i1 = pk[j] & 15;
            int p = (i1 < 4) ? (int)((rlo >> (i1 * 16)) & 0xFFFF)
                             : (int)((rhi >> ((i1 - 4) * 16)) & 0xFFFF);
            pos1[j] = p;
            if (i1 < 4) rlo += 1ULL << (i1 * 16); else rhi += 1ULL << ((i1 - 4) * 16);
        }
    }
    __syncthreads();  // protect sl/sh + count1 before reuse

    // ---- pass 2: top-2 positions (only thresholded tokens count) ----
    lo = 0; hi = 0;
#pragma unroll
    for (int j = 0; j < 8; j++) {
        if (pk[j] >> 8) {
            int i2 = (pk[j] >> 4) & 15;
            if (i2 < 4) lo += 1ULL << (i2 * 16); else hi += 1ULL << ((i2 - 4) * 16);
        }
    }
    mylo = lo; myhi = hi;
    sl[tid] = lo; sh[tid] = hi;
    __syncthreads();
    for (int o = 1; o < 256; o <<= 1) {
        unsigned long long a = 0, c = 0;
        if (tid >= o) { a = sl[tid - o]; c = sh[tid - o]; }
        __syncthreads();
        if (tid >= o) { sl[tid] += a; sh[tid] += c; }
        __syncthreads();
    }
    exlo = sl[tid] - mylo; exhi = sh[tid] - myhi;

    unsigned long long rlo = exlo, rhi = exhi;
#pragma unroll
    for (int j = 0; j < 8; j++) {
        int t = base + j;
        int i1 = pk[j] & 15, i2 = (pk[j] >> 4) & 15, use2 = pk[j] >> 8;
        int off1 = (pos1[j] < CAP) ? i1 * CAP + pos1[j] : -1;
        int off2 = -1;
        if (use2) {
            int p = (i2 < 4) ? (int)((rlo >> (i2 * 16)) & 0xFFFF)
                             : (int)((rhi >> ((i2 - 4) * 16)) & 0xFFFF);
            int pos2 = count1[i2] + p;
            if (pos2 < CAP) off2 = i2 * CAP + pos2;
            if (i2 < 4) rlo += 1ULL << (i2 * 16); else rhi += 1ULL << ((i2 - 4) * 16);
        }
        g_off[t] = make_int2(off1, off2);
    }
}

// ---------------------------------------------------------------------------
// K3: write full output (zeros + inline scatter), one store per byte.
// 2 tokens per 256-thread block; 5 float4 stores per thread.
// ---------------------------------------------------------------------------
__global__ __launch_bounds__(256) void k_write(float* __restrict__ out) {
    int tid = threadIdx.x;
    int t = blockIdx.x * 2 + (tid >> 7);
    int lane = tid & 127;

    int2 off = g_off[t];
    float2 g = g_gates[t];
    float4* o4 = (float4*)out + (size_t)t * F4_PER_TOK;

    int q1 = off.x >> 2, r1 = off.x & 3;   // off=-1 -> q=-1, never matches
    int q2 = off.y >> 2, r2 = off.y & 3;

#pragma unroll
    for (int i = 0; i < 5; i++) {
        int j = lane + i * 128;
        float4 z = make_float4(0.f, 0.f, 0.f, 0.f);
        if (j == q1) ((float*)&z)[r1] = g.x;
        if (j == q2) ((float*)&z)[r2] = g.y;
        o4[j] = z;
    }
}

extern "C" void kernel_launch(void* const* d_in, const int* in_sizes, int n_in,
                              void* d_out, int out_size) {
    const float* x = (const float*)d_in[0];
    const float* w = (const float*)d_in[1];
    float* out = (float*)d_out;

    k_gate<<<NTOK / 8, 256>>>(x, w);
    k_scan<<<B, 256>>>();
    k_write<<<NTOK / 2, 256>>>(out);
}

// round 2
// speedup vs baseline: 1.2053x; 1.2053x over previous
#include <cuda_runtime.h>
#include <cuda_bf16.h>

// Problem constants
#define B 8
#define N 2048
#define D 1024
#define G 8
#define CAP 320
#define NTOK (B*N)            // 16384
#define F4_PER_TOK (G*CAP/4)  // 640
#define TB 32                 // tokens per k_gate block

// Scratch (device globals; no allocation allowed)
__device__ int    g_pack[NTOK];   // i1 | i2<<4 | use2<<8
__device__ float2 g_gates[NTOK];  // (g1n, g2n)
__device__ int2   g_off[NTOK];    // flat offsets within token slab, -1 if dropped

// ---------------------------------------------------------------------------
// K1 v2: register-resident W, zero LDS in the mainloop.
// 256 threads = 8 warps; warp w owns k-strip [w*128, w*128+128); lane owns 4 k.
// Each thread keeps its 8x4 W coefficients in registers (loop-invariant).
// Per token: 1 LDG.128 + 32 FFMA + 9-shuffle expert-splitting butterfly.
// ---------------------------------------------------------------------------
__global__ __launch_bounds__(256) void k_gate(const float* __restrict__ x,
                                              const float* __restrict__ w) {
    __shared__ float part[G * 8 * TB];   // [(e*8+warp)*TB + t], 8 KB

    int tid = threadIdx.x;
    int warp = tid >> 5, lane = tid & 31;
    int k0 = warp * 128 + lane * 4;      // this thread's 4 k-values (fixed)

    // Load W coefficients for owned k's into registers: w is [D, G] row-major,
    // rows k0..k0+3 are 32 contiguous floats.
    float4 wv0 = *(const float4*)(w + k0 * G + 0);
    float4 wv1 = *(const float4*)(w + k0 * G + 4);
    float4 wv2 = *(const float4*)(w + k0 * G + 8);
    float4 wv3 = *(const float4*)(w + k0 * G + 12);
    float4 wv4 = *(const float4*)(w + k0 * G + 16);
    float4 wv5 = *(const float4*)(w + k0 * G + 20);
    float4 wv6 = *(const float4*)(w + k0 * G + 24);
    float4 wv7 = *(const float4*)(w + k0 * G + 28);
    // wreg[e][j] = W[k0+j][e]
    float wreg[G][4];
    wreg[0][0]=wv0.x; wreg[1][0]=wv0.y; wreg[2][0]=wv0.z; wreg[3][0]=wv0.w;
    wreg[4][0]=wv1.x; wreg[5][0]=wv1.y; wreg[6][0]=wv1.z; wreg[7][0]=wv1.w;
    wreg[0][1]=wv2.x; wreg[1][1]=wv2.y; wreg[2][1]=wv2.z; wreg[3][1]=wv2.w;
    wreg[4][1]=wv3.x; wreg[5][1]=wv3.y; wreg[6][1]=wv3.z; wreg[7][1]=wv3.w;
    wreg[0][2]=wv4.x; wreg[1][2]=wv4.y; wreg[2][2]=wv4.z; wreg[3][2]=wv4.w;
    wreg[4][2]=wv5.x; wreg[5][2]=wv5.y; wreg[6][2]=wv5.z; wreg[7][2]=wv5.w;
    wreg[0][3]=wv6.x; wreg[1][3]=wv6.y; wreg[2][3]=wv6.z; wreg[3][3]=wv6.w;
    wreg[4][3]=wv7.x; wreg[5][3]=wv7.y; wreg[6][3]=wv7.z; wreg[7][3]=wv7.w;

    int tok0 = blockIdx.x * TB;
    const unsigned FULL = 0xffffffffu;

    // lane -> expert mapping after the butterfly (lane bits 0,1,2)
    int bit0 = lane & 1;
    int my_e = (lane & 1) * 4 + (lane & 2) + ((lane >> 2) & 1);

#pragma unroll 4
    for (int t = 0; t < TB; t++) {
        const float4 xv = *(const float4*)(x + (size_t)(tok0 + t) * D + k0);

        float acc[G];
#pragma unroll
        for (int e = 0; e < G; e++) {
            acc[e] = fmaf(xv.x, wreg[e][0],
                     fmaf(xv.y, wreg[e][1],
                     fmaf(xv.z, wreg[e][2],
                          xv.w * wreg[e][3])));
        }

        // Stage A (xor 1): 8 -> 4 values; bit0=0 keeps e0-3, bit0=1 keeps e4-7
        float a0 = (bit0 ? acc[4] : acc[0]) + __shfl_xor_sync(FULL, bit0 ? acc[0] : acc[4], 1);
        float a1 = (bit0 ? acc[5] : acc[1]) + __shfl_xor_sync(FULL, bit0 ? acc[1] : acc[5], 1);
        float a2 = (bit0 ? acc[6] : acc[2]) + __shfl_xor_sync(FULL, bit0 ? acc[2] : acc[6], 1);
        float a3 = (bit0 ? acc[7] : acc[3]) + __shfl_xor_sync(FULL, bit0 ? acc[3] : acc[7], 1);
        // Stage B (xor 2): 4 -> 2
        int bit1 = (lane >> 1) & 1;
        float b0 = (bit1 ? a2 : a0) + __shfl_xor_sync(FULL, bit1 ? a0 : a2, 2);
        float b1 = (bit1 ? a3 : a1) + __shfl_xor_sync(FULL, bit1 ? a1 : a3, 2);
        // Stage C (xor 4): 2 -> 1
        int bit2 = (lane >> 2) & 1;
        float c = (bit2 ? b1 : b0) + __shfl_xor_sync(FULL, bit2 ? b0 : b1, 4);
        // Stage D: reduce across lane bits 3,4 (same expert)
        c += __shfl_xor_sync(FULL, c, 8);
        c += __shfl_xor_sync(FULL, c, 16);

        if (lane < 8)
            part[(my_e * 8 + warp) * TB + t] = c;
    }
    __syncthreads();

    // Finalize: one thread per token
    if (tid < TB) {
        int t = tid;
        float p[G];
#pragma unroll
        for (int e = 0; e < G; e++) {
            float s = 0.f;
#pragma unroll
            for (int wq = 0; wq < 8; wq++) s += part[(e * 8 + wq) * TB + t];
            p[e] = s;
        }
        float m = p[0];
#pragma unroll
        for (int e = 1; e < G; e++) m = fmaxf(m, p[e]);
        float s = 0.f;
#pragma unroll
        for (int e = 0; e < G; e++) { p[e] = expf(p[e] - m); s += p[e]; }
        float inv = 1.f / s;
#pragma unroll
        for (int e = 0; e < G; e++) p[e] *= inv;

        int i1 = 0; float g1 = p[0];
#pragma unroll
        for (int e = 1; e < G; e++) if (p[e] > g1) { g1 = p[e]; i1 = e; }
        int i2 = 0; float g2 = -1.f;
#pragma unroll
        for (int e = 0; e < G; e++)
            if (e != i1 && p[e] > g2) { g2 = p[e]; i2 = e; }

        float g1n = g1 / (g1 + g2 + 1e-9f);
        float g2n = g2 / (g1n + g2 + 1e-9f);
        int use2 = (g2n > 0.2f) ? 1 : 0;

        int tok = tok0 + t;
        g_pack[tok] = i1 | (i2 << 4) | (use2 << 8);
        g_gates[tok] = make_float2(g1n, g2n);
    }
}

// ---------------------------------------------------------------------------
// K2: per-batch token scan. 1 block per batch, 256 threads x 8 tokens each.
// 8 expert counters packed as 2 x u64 (16 bits/expert, max 2048 fits).
// ---------------------------------------------------------------------------
__global__ __launch_bounds__(256) void k_scan() {
    __shared__ unsigned long long sl[256], sh[256];
    __shared__ int count1[G];

    int b = blockIdx.x, tid = threadIdx.x;
    int base = b * N + tid * 8;

    int pk[8];
#pragma unroll
    for (int j = 0; j < 8; j++) pk[j] = g_pack[base + j];

    // ---- pass 1: top-1 positions ----
    unsigned long long lo = 0, hi = 0;
#pragma unroll
    for (int j = 0; j < 8; j++) {
        int i1 = pk[j] & 15;
        if (i1 < 4) lo += 1ULL << (i1 * 16); else hi += 1ULL << ((i1 - 4) * 16);
    }
    unsigned long long mylo = lo, myhi = hi;
    sl[tid] = lo; sh[tid] = hi;
    __syncthreads();
    for (int o = 1; o < 256; o <<= 1) {
        unsigned long long a = 0, c = 0;
        if (tid >= o) { a = sl[tid - o]; c = sh[tid - o]; }
        __syncthreads();
        if (tid >= o) { sl[tid] += a; sh[tid] += c; }
        __syncthreads();
    }
    unsigned long long exlo = sl[tid] - mylo, exhi = sh[tid] - myhi;
    if (tid == 255) {
#pragma unroll
        for (int e = 0; e < 4; e++) {
            count1[e]     = min((int)((sl[255] >> (e * 16)) & 0xFFFF), CAP);
            count1[e + 4] = min((int)((sh[255] >> (e * 16)) & 0xFFFF), CAP);
        }
    }
    int pos1[8];
    {
        unsigned long long rlo = exlo, rhi = exhi;
#pragma unroll
        for (int j = 0; j < 8; j++) {
            int i1 = pk[j] & 15;
            int p = (i1 < 4) ? (int)((rlo >> (i1 * 16)) & 0xFFFF)
                             : (int)((rhi >> ((i1 - 4) * 16)) & 0xFFFF);
            pos1[j] = p;
            if (i1 < 4) rlo += 1ULL << (i1 * 16); else rhi += 1ULL << ((i1 - 4) * 16);
        }
    }
    __syncthreads();  // protect sl/sh + count1 before reuse

    // ---- pass 2: top-2 positions (only thresholded tokens count) ----
    lo = 0; hi = 0;
#pragma unroll
    for (int j = 0; j < 8; j++) {
        if (pk[j] >> 8) {
            int i2 = (pk[j] >> 4) & 15;
            if (i2 < 4) lo += 1ULL << (i2 * 16); else hi += 1ULL << ((i2 - 4) * 16);
        }
    }
    mylo = lo; myhi = hi;
    sl[tid] = lo; sh[tid] = hi;
    __syncthreads();
    for (int o = 1; o < 256; o <<= 1) {
        unsigned long long a = 0, c = 0;
        if (tid >= o) { a = sl[tid - o]; c = sh[tid - o]; }
        __syncthreads();
        if (tid >= o) { sl[tid] += a; sh[tid] += c; }
        __syncthreads();
    }
    exlo = sl[tid] - mylo; exhi = sh[tid] - myhi;

    unsigned long long rlo = exlo, rhi = exhi;
#pragma unroll
    for (int j = 0; j < 8; j++) {
        int t = base + j;
        int i1 = pk[j] & 15, i2 = (pk[j] >> 4) & 15, use2 = pk[j] >> 8;
        int off1 = (pos1[j] < CAP) ? i1 * CAP + pos1[j] : -1;
        int off2 = -1;
        if (use2) {
            int p = (i2 < 4) ? (int)((rlo >> (i2 * 16)) & 0xFFFF)
                             : (int)((rhi >> ((i2 - 4) * 16)) & 0xFFFF);
            int pos2 = count1[i2] + p;
            if (pos2 < CAP) off2 = i2 * CAP + pos2;
            if (i2 < 4) rlo += 1ULL << (i2 * 16); else rhi += 1ULL << ((i2 - 4) * 16);
        }
        g_off[t] = make_int2(off1, off2);
    }
}

// ---------------------------------------------------------------------------
// K3: write full output (zeros + inline scatter), one store per byte.
// 2 tokens per 256-thread block; 5 float4 stores per thread.
// ---------------------------------------------------------------------------
__global__ __launch_bounds__(256) void k_write(float* __restrict__ out) {
    int tid = threadIdx.x;
    int t = blockIdx.x * 2 + (tid >> 7);
    int lane = tid & 127;

    int2 off = g_off[t];
    float2 g = g_gates[t];
    float4* o4 = (float4*)out + (size_t)t * F4_PER_TOK;

    int q1 = off.x >> 2, r1 = off.x & 3;   // off=-1 -> q=-1, never matches
    int q2 = off.y >> 2, r2 = off.y & 3;

#pragma unroll
    for (int i = 0; i < 5; i++) {
        int j = lane + i * 128;
        float4 z = make_float4(0.f, 0.f, 0.f, 0.f);
        if (j == q1) ((float*)&z)[r1] = g.x;
        if (j == q2) ((float*)&z)[r2] = g.y;
        o4[j] = z;
    }
}

extern "C" void kernel_launch(void* const* d_in, const int* in_sizes, int n_in,
                              void* d_out, int out_size) {
    const float* x = (const float*)d_in[0];
    const float* w = (const float*)d_in[1];
    float* out = (float*)d_out;

    k_gate<<<NTOK / TB, 256>>>(x, w);
    k_scan<<<B, 256>>>();
    k_write<<<NTOK / 2, 256>>>(out);
}

// round 3
// speedup vs baseline: 1.2080x; 1.0022x over previous
#include <cuda_runtime.h>
#include <cuda_bf16.h>

// Problem constants
#define B 8
#define N 2048
#define D 1024
#define G 8
#define CAP 320
#define NTOK (B*N)            // 16384
#define SLAB (G*CAP)          // 2560 floats per token
#define TB 32                 // tokens per k_gate block
#define ZBLK (NTOK*SLAB/4/512) // 20480 float4 zeroed per block (512 blocks)

// Scratch (device globals; no allocation allowed)
__device__ int    g_pack[NTOK];   // i1 | i2<<4 | use2<<8
__device__ float2 g_gates[NTOK];  // (g1n, g2n)
__device__ int2   g_off[NTOK];    // flat offsets within token slab, -1 if dropped

// ---------------------------------------------------------------------------
// K1: gating (register-resident W, k-split + shuffle butterfly) FUSED with
// zero-fill of the entire output. The zero stores are independent of the
// gating math and stream into DRAM while the compute is stalled on loads.
// Each block zeros its own 20480-float4 slice: 80 float4 per thread,
// 2 per token-iteration + 16 in a tail loop.
// ---------------------------------------------------------------------------
__global__ __launch_bounds__(256) void k_gate_zero(const float* __restrict__ x,
                                                   const float* __restrict__ w,
                                                   float* __restrict__ out) {
    __shared__ float part[G * 8 * TB];   // [(e*8+warp)*TB + t], 8 KB

    int tid = threadIdx.x;
    int warp = tid >> 5, lane = tid & 31;
    int k0 = warp * 128 + lane * 4;      // this thread's 4 k-values (fixed)

    // W coefficients for owned k's -> registers (w is [D, G] row-major)
    float4 wv0 = *(const float4*)(w + k0 * G + 0);
    float4 wv1 = *(const float4*)(w + k0 * G + 4);
    float4 wv2 = *(const float4*)(w + k0 * G + 8);
    float4 wv3 = *(const float4*)(w + k0 * G + 12);
    float4 wv4 = *(const float4*)(w + k0 * G + 16);
    float4 wv5 = *(const float4*)(w + k0 * G + 20);
    float4 wv6 = *(const float4*)(w + k0 * G + 24);
    float4 wv7 = *(const float4*)(w + k0 * G + 28);
    float wreg[G][4];
    wreg[0][0]=wv0.x; wreg[1][0]=wv0.y; wreg[2][0]=wv0.z; wreg[3][0]=wv0.w;
    wreg[4][0]=wv1.x; wreg[5][0]=wv1.y; wreg[6][0]=wv1.z; wreg[7][0]=wv1.w;
    wreg[0][1]=wv2.x; wreg[1][1]=wv2.y; wreg[2][1]=wv2.z; wreg[3][1]=wv2.w;
    wreg[4][1]=wv3.x; wreg[5][1]=wv3.y; wreg[6][1]=wv3.z; wreg[7][1]=wv3.w;
    wreg[0][2]=wv4.x; wreg[1][2]=wv4.y; wreg[2][2]=wv4.z; wreg[3][2]=wv4.w;
    wreg[4][2]=wv5.x; wreg[5][2]=wv5.y; wreg[6][2]=wv5.z; wreg[7][2]=wv5.w;
    wreg[0][3]=wv6.x; wreg[1][3]=wv6.y; wreg[2][3]=wv6.z; wreg[3][3]=wv6.w;
    wreg[4][3]=wv7.x; wreg[5][3]=wv7.y; wreg[6][3]=wv7.z; wreg[7][3]=wv7.w;

    int tok0 = blockIdx.x * TB;
    const unsigned FULL = 0xffffffffu;

    // zero-fill slice for this block
    float4* zbase = (float4*)out + (size_t)blockIdx.x * ZBLK + tid;
    const float4 ZV = make_float4(0.f, 0.f, 0.f, 0.f);

    int bit0 = lane & 1;
    int my_e = (lane & 1) * 4 + (lane & 2) + ((lane >> 2) & 1);

#pragma unroll 4
    for (int t = 0; t < TB; t++) {
        const float4 xv = *(const float4*)(x + (size_t)(tok0 + t) * D + k0);

        // interleaved zero stores (independent of gating)
        zbase[(t * 2 + 0) * 256] = ZV;
        zbase[(t * 2 + 1) * 256] = ZV;

        float acc[G];
#pragma unroll
        for (int e = 0; e < G; e++) {
            acc[e] = fmaf(xv.x, wreg[e][0],
                     fmaf(xv.y, wreg[e][1],
                     fmaf(xv.z, wreg[e][2],
                          xv.w * wreg[e][3])));
        }

        // Stage A (xor 1): 8 -> 4
        float a0 = (bit0 ? acc[4] : acc[0]) + __shfl_xor_sync(FULL, bit0 ? acc[0] : acc[4], 1);
        float a1 = (bit0 ? acc[5] : acc[1]) + __shfl_xor_sync(FULL, bit0 ? acc[1] : acc[5], 1);
        float a2 = (bit0 ? acc[6] : acc[2]) + __shfl_xor_sync(FULL, bit0 ? acc[2] : acc[6], 1);
        float a3 = (bit0 ? acc[7] : acc[3]) + __shfl_xor_sync(FULL, bit0 ? acc[3] : acc[7], 1);
        // Stage B (xor 2): 4 -> 2
        int bit1 = (lane >> 1) & 1;
        float b0 = (bit1 ? a2 : a0) + __shfl_xor_sync(FULL, bit1 ? a0 : a2, 2);
        float b1 = (bit1 ? a3 : a1) + __shfl_xor_sync(FULL, bit1 ? a1 : a3, 2);
        // Stage C (xor 4): 2 -> 1
        int bit2 = (lane >> 2) & 1;
        float c = (bit2 ? b1 : b0) + __shfl_xor_sync(FULL, bit2 ? b0 : b1, 4);
        // Stage D: combine lane groups (same expert)
        c += __shfl_xor_sync(FULL, c, 8);
        c += __shfl_xor_sync(FULL, c, 16);

        if (lane < 8)
            part[(my_e * 8 + warp) * TB + t] = c;
    }
    // tail of zero slice: indices 64..79
#pragma unroll
    for (int j = 64; j < 80; j++)
        zbase[j * 256] = ZV;

    __syncthreads();

    // Finalize: one thread per token
    if (tid < TB) {
        int t = tid;
        float p[G];
#pragma unroll
        for (int e = 0; e < G; e++) {
            float s = 0.f;
#pragma unroll
            for (int wq = 0; wq < 8; wq++) s += part[(e * 8 + wq) * TB + t];
            p[e] = s;
        }
        float m = p[0];
#pragma unroll
        for (int e = 1; e < G; e++) m = fmaxf(m, p[e]);
        float s = 0.f;
#pragma unroll
        for (int e = 0; e < G; e++) { p[e] = expf(p[e] - m); s += p[e]; }
        float inv = 1.f / s;
#pragma unroll
        for (int e = 0; e < G; e++) p[e] *= inv;

        int i1 = 0; float g1 = p[0];
#pragma unroll
        for (int e = 1; e < G; e++) if (p[e] > g1) { g1 = p[e]; i1 = e; }
        int i2 = 0; float g2 = -1.f;
#pragma unroll
        for (int e = 0; e < G; e++)
            if (e != i1 && p[e] > g2) { g2 = p[e]; i2 = e; }

        float g1n = g1 / (g1 + g2 + 1e-9f);
        float g2n = g2 / (g1n + g2 + 1e-9f);
        int use2 = (g2n > 0.2f) ? 1 : 0;

        int tok = tok0 + t;
        g_pack[tok] = i1 | (i2 << 4) | (use2 << 8);
        g_gates[tok] = make_float2(g1n, g2n);
    }
}

// ---------------------------------------------------------------------------
// K2: per-batch token scan. 1 block per batch, 256 threads x 8 tokens each.
// 8 expert counters packed as 2 x u64 (16 bits/expert, max 2048 fits).
// ---------------------------------------------------------------------------
__global__ __launch_bounds__(256) void k_scan() {
    __shared__ unsigned long long sl[256], sh[256];
    __shared__ int count1[G];

    int b = blockIdx.x, tid = threadIdx.x;
    int base = b * N + tid * 8;

    int pk[8];
#pragma unroll
    for (int j = 0; j < 8; j++) pk[j] = g_pack[base + j];

    // ---- pass 1: top-1 positions ----
    unsigned long long lo = 0, hi = 0;
#pragma unroll
    for (int j = 0; j < 8; j++) {
        int i1 = pk[j] & 15;
        if (i1 < 4) lo += 1ULL << (i1 * 16); else hi += 1ULL << ((i1 - 4) * 16);
    }
    unsigned long long mylo = lo, myhi = hi;
    sl[tid] = lo; sh[tid] = hi;
    __syncthreads();
    for (int o = 1; o < 256; o <<= 1) {
        unsigned long long a = 0, c = 0;
        if (tid >= o) { a = sl[tid - o]; c = sh[tid - o]; }
        __syncthreads();
        if (tid >= o) { sl[tid] += a; sh[tid] += c; }
        __syncthreads();
    }
    unsigned long long exlo = sl[tid] - mylo, exhi = sh[tid] - myhi;
    if (tid == 255) {
#pragma unroll
        for (int e = 0; e < 4; e++) {
            count1[e]     = min((int)((sl[255] >> (e * 16)) & 0xFFFF), CAP);
            count1[e + 4] = min((int)((sh[255] >> (e * 16)) & 0xFFFF), CAP);
        }
    }
    int pos1[8];
    {
        unsigned long long rlo = exlo, rhi = exhi;
#pragma unroll
        for (int j = 0; j < 8; j++) {
            int i1 = pk[j] & 15;
            int p = (i1 < 4) ? (int)((rlo >> (i1 * 16)) & 0xFFFF)
                             : (int)((rhi >> ((i1 - 4) * 16)) & 0xFFFF);
            pos1[j] = p;
            if (i1 < 4) rlo += 1ULL << (i1 * 16); else rhi += 1ULL << ((i1 - 4) * 16);
        }
    }
    __syncthreads();  // protect sl/sh + count1 before reuse

    // ---- pass 2: top-2 positions (only thresholded tokens count) ----
    lo = 0; hi = 0;
#pragma unroll
    for (int j = 0; j < 8; j++) {
        if (pk[j] >> 8) {
            int i2 = (pk[j] >> 4) & 15;
            if (i2 < 4) lo += 1ULL << (i2 * 16); else hi += 1ULL << ((i2 - 4) * 16);
        }
    }
    mylo = lo; myhi = hi;
    sl[tid] = lo; sh[tid] = hi;
    __syncthreads();
    for (int o = 1; o < 256; o <<= 1) {
        unsigned long long a = 0, c = 0;
        if (tid >= o) { a = sl[tid - o]; c = sh[tid - o]; }
        __syncthreads();
        if (tid >= o) { sl[tid] += a; sh[tid] += c; }
        __syncthreads();
    }
    exlo = sl[tid] - mylo; exhi = sh[tid] - myhi;

    unsigned long long rlo = exlo, rhi = exhi;
#pragma unroll
    for (int j = 0; j < 8; j++) {
        int t = base + j;
        int i1 = pk[j] & 15, i2 = (pk[j] >> 4) & 15, use2 = pk[j] >> 8;
        int off1 = (pos1[j] < CAP) ? i1 * CAP + pos1[j] : -1;
        int off2 = -1;
        if (use2) {
            int p = (i2 < 4) ? (int)((rlo >> (i2 * 16)) & 0xFFFF)
                             : (int)((rhi >> ((i2 - 4) * 16)) & 0xFFFF);
            int pos2 = count1[i2] + p;
            if (pos2 < CAP) off2 = i2 * CAP + pos2;
            if (i2 < 4) rlo += 1ULL << (i2 * 16); else rhi += 1ULL << ((i2 - 4) * 16);
        }
        g_off[t] = make_int2(off1, off2);
    }
}

// ---------------------------------------------------------------------------
// K3: tiny scatter — one thread per token, <=2 predicated 4B stores into the
// already-zeroed output.
// ---------------------------------------------------------------------------
__global__ __launch_bounds__(256) void k_scatter(float* __restrict__ out) {
    int t = blockIdx.x * 256 + threadIdx.x;
    int2 off = g_off[t];
    float2 g = g_gates[t];
    float* o = out + (size_t)t * SLAB;
    if (off.x >= 0) o[off.x] = g.x;
    if (off.y >= 0) o[off.y] = g.y;
}

extern "C" void kernel_launch(void* const* d_in, const int* in_sizes, int n_in,
                              void* d_out, int out_size) {
    const float* x = (const float*)d_in[0];
    const float* w = (const float*)d_in[1];
    float* out = (float*)d_out;

    k_gate_zero<<<NTOK / TB, 256>>>(x, w, out);
    k_scan<<<B, 256>>>();
    k_scatter<<<NTOK / 256, 256>>>(out);
}